// round 11
// baseline (speedup 1.0000x reference)
#include <cuda_runtime.h>
#include <cuda_fp16.h>
#include <cstdint>

// MinHashSketch: sketch[s][h] = min over nodes m in segment s of dot(x[m], H[h]),
// empty segments -> 0.  x:[500000,256] f32, batch:[500000] i64/i32 (detected),
// H:[128,256] f32, out:[512,128] f32.
//
// Persistent mma.sync m16n8k16 FP16 GEMM. A fragments are loaded DIRECTLY from
// global memory (k-permuted so each lane's fragment is one LDG.128), converted
// to fp16 in registers; B (=H) staged once per CTA in fragment smem. No smem
// A pipeline, no syncs in the tile loop: warps run fully decoupled.
// Fused segment-min epilogue, order-preserving uint encoding + atomicMin.

#define NODES 500000
#define FDIM 256
#define NH   128
#define NSEG 512

#define BM   128
#define NKS  (FDIM / 16)        // 16 k-steps of k16
#define THREADS 256
#define NTILES ((NODES + BM - 1) / BM)   // 3907

// B fragment smem (b32 words, 2 fp16 per word):
//  8 n-pairs * 16 ks * 132 words = 16896 words (~68 KB), paired layout -> LDS.128
#define B_KS_STRIDE   132
#define B_PAIR_STRIDE (NKS * B_KS_STRIDE)    // 2112
#define SM_B_WORDS    (8 * B_PAIR_STRIDE)    // 16896
#define SMEM_BYTES    (SM_B_WORDS * 4)

__device__ __forceinline__ unsigned fenc(float f) {
    unsigned u = __float_as_uint(f);
    return (u & 0x80000000u) ? ~u : (u | 0x80000000u);
}

__device__ __forceinline__ unsigned packh2(float lo, float hi) {
    __half2 h = __floats2half2_rn(lo, hi);
    return *reinterpret_cast<unsigned*>(&h);
}

__device__ __forceinline__ void mma16(float* c, const unsigned* a, const unsigned* b) {
    asm volatile(
        "mma.sync.aligned.m16n8k16.row.col.f32.f16.f16.f32 "
        "{%0,%1,%2,%3}, {%4,%5,%6,%7}, {%8,%9}, {%0,%1,%2,%3};"
        : "+f"(c[0]), "+f"(c[1]), "+f"(c[2]), "+f"(c[3])
        : "r"(a[0]), "r"(a[1]), "r"(a[2]), "r"(a[3]), "r"(b[0]), "r"(b[1]));
}

__global__ void init_kernel(unsigned* outu) {
    int i = blockIdx.x * blockDim.x + threadIdx.x;
    if (i < NSEG * NH) outu[i] = 0xFFFFFFFFu;
}

__global__ void decode_kernel(float* out) {
    int i = blockIdx.x * blockDim.x + threadIdx.x;
    if (i < NSEG * NH) {
        unsigned u = __float_as_uint(out[i]);
        float f;
        if (u == 0xFFFFFFFFu) f = 0.0f;   // empty segment -> 0
        else f = (u & 0x80000000u) ? __uint_as_float(u ^ 0x80000000u) : __uint_as_float(~u);
        out[i] = f;
    }
}

__global__ void __launch_bounds__(THREADS, 1)
mm_kernel(const float* __restrict__ x, const void* __restrict__ batch_raw,
          const float* __restrict__ H, unsigned* __restrict__ outu) {
    extern __shared__ unsigned Bfu[];
    const int tid = threadIdx.x;
    const int wid = tid >> 5, lane = tid & 31;
    const int wm = wid >> 1, wn = wid & 1;       // 4 (m) x 2 (n) warp grid
    const int g = lane >> 2, tt = lane & 3;

    // batch dtype: int64 -> int32 word[NODES-1] is a hi-word == 0;
    // int32 -> it's the max sorted segment id (nonzero w.h.p.).
    const int is64 = (((const int*)batch_raw)[NODES - 1] == 0);

    // Stage B = H once. Physical k-permutation: lane t's logical k
    // {2t,2t+1,2t+8,2t+9} lives at physical cols {4t..4t+3}, so each H float4
    // is exactly one lane's (b0,b1) pair.
    for (int i = tid; i < (NH * FDIM) / 4; i += THREADS) {
        int n = i >> 6;                 // 64 float4 per H row
        int col4 = i & 63;
        int ks = col4 >> 2, t4 = col4 & 3;
        float4 v = ((const float4*)H)[i];
        int pp = n >> 4, half = (n >> 3) & 1;
        int lane0 = ((n & 7) << 2) | t4;
        unsigned* b = Bfu + pp * B_PAIR_STRIDE + ks * B_KS_STRIDE + lane0 * 4 + half * 2;
        b[0] = packh2(v.x, v.y);        // logical k 2t, 2t+1
        b[1] = packh2(v.z, v.w);        // logical k 2t+8, 2t+9
    }
    __syncthreads();

    const unsigned* Bw = Bfu + wn * 4 * B_PAIR_STRIDE + lane * 4;
    const float4 fz = make_float4(0.f, 0.f, 0.f, 0.f);

    // ---------------- persistent tile loop (sync-free) ----------------
    for (int t = blockIdx.x; t < NTILES; t += gridDim.x) {
        const int m0 = t * BM;

        // this warp's four A fragment rows
        int r0 = m0 + wm * 32 + g;
        bool ok[4];
        const float* ap[4];
#pragma unroll
        for (int i = 0; i < 4; i++) {
            int r = r0 + i * 8;
            ok[i] = (r < NODES);
            ap[i] = x + (size_t)(ok[i] ? r : 0) * FDIM + tt * 4;
        }

        float acc[2][8][4];
#pragma unroll
        for (int i = 0; i < 2; i++)
#pragma unroll
            for (int j = 0; j < 8; j++)
#pragma unroll
                for (int c = 0; c < 4; c++) acc[i][j][c] = 0.f;

        // register prefetch pipeline, distance 1
        float4 v[2][4];
#pragma unroll
        for (int i = 0; i < 4; i++)
            v[0][i] = ok[i] ? *(const float4*)(ap[i]) : fz;

#pragma unroll 2
        for (int ks = 0; ks < NKS; ks++) {
            const int cur = ks & 1, nxt = cur ^ 1;
            if (ks + 1 < NKS) {
#pragma unroll
                for (int i = 0; i < 4; i++)
                    v[nxt][i] = ok[i] ? *(const float4*)(ap[i] + (ks + 1) * 16) : fz;
            }
            // A frags: a[mt][0]=row g klo, [1]=row g+8 klo, [2]=row g khi, [3]=row g+8 khi
            unsigned a0[4], a1[4];
            a0[0] = packh2(v[cur][0].x, v[cur][0].y);
            a0[1] = packh2(v[cur][1].x, v[cur][1].y);
            a0[2] = packh2(v[cur][0].z, v[cur][0].w);
            a0[3] = packh2(v[cur][1].z, v[cur][1].w);
            a1[0] = packh2(v[cur][2].x, v[cur][2].y);
            a1[1] = packh2(v[cur][3].x, v[cur][3].y);
            a1[2] = packh2(v[cur][2].z, v[cur][2].w);
            a1[3] = packh2(v[cur][3].z, v[cur][3].w);

            unsigned b[8][2];
#pragma unroll
            for (int q = 0; q < 4; q++) {
                uint4 bv = *(const uint4*)(Bw + q * B_PAIR_STRIDE + ks * B_KS_STRIDE);
                b[2 * q][0]     = bv.x;
                b[2 * q][1]     = bv.y;
                b[2 * q + 1][0] = bv.z;
                b[2 * q + 1][1] = bv.w;
            }
#pragma unroll
            for (int j = 0; j < 8; j++) {
                mma16(acc[0][j], a0, b[j]);
                mma16(acc[1][j], a1, b[j]);
            }
        }

        // ---- fused segment-min epilogue (no smem, no sync) ----
        bool full = (m0 + BM) <= NODES;
        int sF = is64 ? (int)((const long long*)batch_raw)[m0]
                      : ((const int*)batch_raw)[m0];
        int sL = -2;
        if (full)
            sL = is64 ? (int)((const long long*)batch_raw)[m0 + BM - 1]
                      : ((const int*)batch_raw)[m0 + BM - 1];

        if (full && sF == sL) {
            // one segment: shuffle-reduce column mins, 1 atomic per (col, m-warp)
#pragma unroll
            for (int j = 0; j < 8; j++) {
                float v0 = fminf(fminf(acc[0][j][0], acc[0][j][2]),
                                 fminf(acc[1][j][0], acc[1][j][2]));
                float v1 = fminf(fminf(acc[0][j][1], acc[0][j][3]),
                                 fminf(acc[1][j][1], acc[1][j][3]));
#pragma unroll
                for (int off = 4; off < 32; off <<= 1) {
                    v0 = fminf(v0, __shfl_xor_sync(0xffffffffu, v0, off));
                    v1 = fminf(v1, __shfl_xor_sync(0xffffffffu, v1, off));
                }
                if (lane < 4) {
                    int col = wn * 64 + j * 8 + lane * 2;
                    atomicMin(&outu[sF * NH + col],     fenc(v0));
                    atomicMin(&outu[sF * NH + col + 1], fenc(v1));
                }
            }
        } else {
            // boundary / tail tile: per-element atomicMin, segs loaded directly
#pragma unroll
            for (int i = 0; i < 2; i++) {
#pragma unroll
                for (int h = 0; h < 2; h++) {
                    int m = m0 + wm * 32 + i * 16 + g + h * 8;
                    if (m < NODES) {
                        int s = is64 ? (int)((const long long*)batch_raw)[m]
                                     : ((const int*)batch_raw)[m];
                        unsigned* dst = outu + s * NH + wn * 64 + tt * 2;
#pragma unroll
                        for (int j = 0; j < 8; j++) {
                            atomicMin(dst + j * 8,     fenc(acc[i][j][h * 2 + 0]));
                            atomicMin(dst + j * 8 + 1, fenc(acc[i][j][h * 2 + 1]));
                        }
                    }
                }
            }
        }
    }
}

extern "C" void kernel_launch(void* const* d_in, const int* in_sizes, int n_in,
                              void* d_out, int out_size) {
    const float* x = nullptr;
    const void* batch = nullptr;
    const float* H = nullptr;
    for (int i = 0; i < n_in; i++) {
        int s = in_sizes[i];
        if (s == NODES * FDIM) x = (const float*)d_in[i];
        else if (s == NODES) batch = d_in[i];
        else if (s == NH * FDIM) H = (const float*)d_in[i];
    }
    unsigned* outu = (unsigned*)d_out;

    int nsm = 148;
    cudaDeviceGetAttribute(&nsm, cudaDevAttrMultiProcessorCount, 0);
    cudaFuncSetAttribute(mm_kernel, cudaFuncAttributeMaxDynamicSharedMemorySize, SMEM_BYTES);

    init_kernel<<<(NSEG * NH + 255) / 256, 256>>>(outu);
    mm_kernel<<<nsm, THREADS, SMEM_BYTES>>>(x, batch, H, outu);
    decode_kernel<<<(NSEG * NH + 255) / 256, 256>>>((float*)d_out);
}

// round 13
// speedup vs baseline: 1.2571x; 1.2571x over previous
#include <cuda_runtime.h>
#include <cuda_fp16.h>
#include <cstdint>

// MinHashSketch: sketch[s][h] = min over nodes m in segment s of dot(x[m], H[h]),
// empty segments -> 0.  x:[500000,256] f32, batch:[500000] i64/i32 (detected),
// H:[128,256] f32, out:[512,128] f32.
//
// Warp-specialized persistent fp16 m16n8k16 GEMM:
//   warps 4-7 (producers): LDG x -> cvt fp16 -> STS fragment-layout A chunks
//                          (BK=64) into a 2-deep ring, distance-1 prefetch.
//   warps 0-3 (consumers): LDS + mma only (mt4 x nt8 each), plus fused
//                          segment-min epilogue overlapped with producer stream.
// B (=H) staged once per CTA. One barrier per chunk. Order-preserving uint
// encoding + atomicMin for the global segment-min.

#define NODES 500000
#define FDIM 256
#define NH   128
#define NSEG 512

#define BM   128
#define BK   64
#define CPT  (FDIM / BK)          // 4 chunks per tile
#define NKS  (FDIM / 16)          // 16 global k-steps
#define THREADS 256
#define NTILES ((NODES + BM - 1) / BM)   // 3907

// B fragment smem (b32 words, 2 fp16/word): 8 n-pairs * 16 ks * 132
#define B_KS_STRIDE   132
#define B_PAIR_STRIDE (NKS * B_KS_STRIDE)    // 2112
#define SM_B_WORDS    (8 * B_PAIR_STRIDE)    // 16896
// A fragment smem: per chunk 8 mt * 4 ksl * 132; 2 buffers
#define A_KS_STRIDE   132
#define A_MT_STRIDE   (4 * A_KS_STRIDE)      // 528
#define A_BUF_WORDS   (8 * A_MT_STRIDE)      // 4224
#define SM_A_OFF      SM_B_WORDS
#define SMEM_BYTES    ((SM_B_WORDS + 2 * A_BUF_WORDS) * 4)   // ~101 KB

__device__ __forceinline__ unsigned fenc(float f) {
    unsigned u = __float_as_uint(f);
    return (u & 0x80000000u) ? ~u : (u | 0x80000000u);
}

__device__ __forceinline__ unsigned packh2(float lo, float hi) {
    __half2 h = __floats2half2_rn(lo, hi);
    return *reinterpret_cast<unsigned*>(&h);
}

__device__ __forceinline__ void mma16(float* c, const unsigned* a, const unsigned* b) {
    asm volatile(
        "mma.sync.aligned.m16n8k16.row.col.f32.f16.f16.f32 "
        "{%0,%1,%2,%3}, {%4,%5,%6,%7}, {%8,%9}, {%0,%1,%2,%3};"
        : "+f"(c[0]), "+f"(c[1]), "+f"(c[2]), "+f"(c[3])
        : "r"(a[0]), "r"(a[1]), "r"(a[2]), "r"(a[3]), "r"(b[0]), "r"(b[1]));
}

__global__ void init_kernel(unsigned* outu) {
    int i = blockIdx.x * blockDim.x + threadIdx.x;
    if (i < NSEG * NH) outu[i] = 0xFFFFFFFFu;
}

__global__ void decode_kernel(float* out) {
    int i = blockIdx.x * blockDim.x + threadIdx.x;
    if (i < NSEG * NH) {
        unsigned u = __float_as_uint(out[i]);
        float f;
        if (u == 0xFFFFFFFFu) f = 0.0f;   // empty segment -> 0
        else f = (u & 0x80000000u) ? __uint_as_float(u ^ 0x80000000u) : __uint_as_float(~u);
        out[i] = f;
    }
}

// ---- producer helpers: chunk = [128 rows x 64 phys cols] of x ----
__device__ __forceinline__ void fetchA(float4* v, const float* __restrict__ x,
                                       int m0, int bk, int ptid) {
#pragma unroll
    for (int it = 0; it < 16; it++) {
        int idx = ptid + it * 128;
        int row = idx >> 4, col4 = idx & 15;
        int m = m0 + row;
        v[it] = (m < NODES)
            ? *(const float4*)(x + (size_t)m * FDIM + bk * BK + col4 * 4)
            : make_float4(0.f, 0.f, 0.f, 0.f);
    }
}

__device__ __forceinline__ void stsA(const float4* v, unsigned* Asm, int buf, int ptid) {
    unsigned* base = Asm + buf * A_BUF_WORDS;
#pragma unroll
    for (int it = 0; it < 16; it++) {
        int idx = ptid + it * 128;
        int row = idx >> 4, col4 = idx & 15;
        int mt = row >> 4, rr = row & 15;
        int g = rr & 7, hi = rr >> 3;
        int ksl = col4 >> 2, t4 = col4 & 3;
        int woff = mt * A_MT_STRIDE + ksl * A_KS_STRIDE + (g * 4 + t4) * 4 + hi * 2;
        uint2 w;
        w.x = packh2(v[it].x, v[it].y);   // klo pair
        w.y = packh2(v[it].z, v[it].w);   // khi pair
        *(uint2*)(base + woff) = w;       // word layout per lane-uint4: {a0,a2,a1,a3}
    }
}

__global__ void __launch_bounds__(THREADS, 1)
mm_kernel(const float* __restrict__ x, const void* __restrict__ batch_raw,
          const float* __restrict__ H, unsigned* __restrict__ outu) {
    extern __shared__ unsigned smw[];
    unsigned* Bfu = smw;
    unsigned* Asm = smw + SM_A_OFF;

    const int tid = threadIdx.x;
    const int wid = tid >> 5, lane = tid & 31;
    const int is64 = (((const int*)batch_raw)[NODES - 1] == 0);

    if (wid >= 4) {
        // ======================= PRODUCERS (warps 4-7) =======================
        const int ptid = tid - 128;
        int tp = blockIdx.x, bkp = 0;
        float4 v[16];
        fetchA(v, x, tp * BM, 0, ptid);
        stsA(v, Asm, 0, ptid);
        bkp = 1;
        fetchA(v, x, tp * BM, bkp, ptid);    // chunk 1 (CPT>=2 always)
        __syncthreads();                      // #0: buf0 full
        int buf = 1;
        for (;;) {
            stsA(v, Asm, buf, ptid);
            if (++bkp == CPT) { bkp = 0; tp += gridDim.x; }
            bool have = (tp < NTILES);
            if (have) fetchA(v, x, tp * BM, bkp, ptid);
            __syncthreads();
            buf ^= 1;
            if (!have) break;
        }
    } else {
        // ======================= CONSUMERS (warps 0-3) =======================
        const int wm = wid >> 1, wn = wid & 1;   // 2 (M) x 2 (N)
        const int tt = lane & 3;

        // Stage B = H once (k-permuted: logical {2t,2t+1,2t+8,2t+9} at phys 4t..4t+3)
        for (int i = tid; i < (NH * FDIM) / 4; i += 128) {
            int n = i >> 6;
            int col4 = i & 63;
            int ks = col4 >> 2, t4 = col4 & 3;
            float4 hv = ((const float4*)H)[i];
            int pp = n >> 4, half = (n >> 3) & 1;
            int lane0 = ((n & 7) << 2) | t4;
            unsigned* b = Bfu + pp * B_PAIR_STRIDE + ks * B_KS_STRIDE + lane0 * 4 + half * 2;
            b[0] = packh2(hv.x, hv.y);
            b[1] = packh2(hv.z, hv.w);
        }
        __syncthreads();                      // #0

        const unsigned* Bw = Bfu + wn * 4 * B_PAIR_STRIDE + lane * 4;
        int buf = 0;

        for (int t = blockIdx.x; t < NTILES; t += gridDim.x) {
            const int m0 = t * BM;
            const bool lastTile = (t + gridDim.x >= NTILES);

            float acc[4][8][4];
#pragma unroll
            for (int i = 0; i < 4; i++)
#pragma unroll
                for (int j = 0; j < 8; j++)
#pragma unroll
                    for (int c = 0; c < 4; c++) acc[i][j][c] = 0.f;

            for (int bk = 0; bk < CPT; bk++) {
                const unsigned* Ab = Asm + buf * A_BUF_WORDS + wm * 4 * A_MT_STRIDE + lane * 4;
#pragma unroll
                for (int ksl = 0; ksl < 4; ksl++) {
                    int ksg = bk * 4 + ksl;
                    uint4 av[4];
#pragma unroll
                    for (int i = 0; i < 4; i++)
                        av[i] = *(const uint4*)(Ab + i * A_MT_STRIDE + ksl * A_KS_STRIDE);
                    unsigned b[8][2];
#pragma unroll
                    for (int q = 0; q < 4; q++) {
                        uint4 bv = *(const uint4*)(Bw + q * B_PAIR_STRIDE + ksg * B_KS_STRIDE);
                        b[2 * q][0] = bv.x;     b[2 * q][1] = bv.y;
                        b[2 * q + 1][0] = bv.z; b[2 * q + 1][1] = bv.w;
                    }
#pragma unroll
                    for (int i = 0; i < 4; i++) {
                        unsigned a[4] = {av[i].x, av[i].z, av[i].y, av[i].w};
#pragma unroll
                        for (int j = 0; j < 8; j++)
                            mma16(acc[i][j], a, b[j]);
                    }
                }
                buf ^= 1;

                if (bk == CPT - 1) {
                    // ---- fused segment-min epilogue (inside last interval) ----
                    bool full = (m0 + BM) <= NODES;
                    int sF = is64 ? (int)((const long long*)batch_raw)[m0]
                                  : ((const int*)batch_raw)[m0];
                    int sL = -2;
                    if (full)
                        sL = is64 ? (int)((const long long*)batch_raw)[m0 + BM - 1]
                                  : ((const int*)batch_raw)[m0 + BM - 1];

                    if (full && sF == sL) {
#pragma unroll
                        for (int j = 0; j < 8; j++) {
                            float v0 = fminf(fminf(acc[0][j][0], acc[0][j][2]),
                                             fminf(acc[1][j][0], acc[1][j][2]));
                            v0 = fminf(v0, fminf(fminf(acc[2][j][0], acc[2][j][2]),
                                                 fminf(acc[3][j][0], acc[3][j][2])));
                            float v1 = fminf(fminf(acc[0][j][1], acc[0][j][3]),
                                             fminf(acc[1][j][1], acc[1][j][3]));
                            v1 = fminf(v1, fminf(fminf(acc[2][j][1], acc[2][j][3]),
                                                 fminf(acc[3][j][1], acc[3][j][3])));
#pragma unroll
                            for (int off = 4; off < 32; off <<= 1) {
                                v0 = fminf(v0, __shfl_xor_sync(0xffffffffu, v0, off));
                                v1 = fminf(v1, __shfl_xor_sync(0xffffffffu, v1, off));
                            }
                            if (lane < 4) {
                                int col = wn * 64 + j * 8 + lane * 2;
                                atomicMin(&outu[sF * NH + col],     fenc(v0));
                                atomicMin(&outu[sF * NH + col + 1], fenc(v1));
                            }
                        }
                    } else {
                        const int g = lane >> 2;
#pragma unroll
                        for (int i = 0; i < 4; i++) {
#pragma unroll
                            for (int h = 0; h < 2; h++) {
                                int m = m0 + wm * 64 + i * 16 + g + h * 8;
                                if (m < NODES) {
                                    int s = is64 ? (int)((const long long*)batch_raw)[m]
                                                 : ((const int*)batch_raw)[m];
                                    unsigned* dst = outu + s * NH + wn * 64 + tt * 2;
#pragma unroll
                                    for (int j = 0; j < 8; j++) {
                                        atomicMin(dst + j * 8,     fenc(acc[i][j][h * 2 + 0]));
                                        atomicMin(dst + j * 8 + 1, fenc(acc[i][j][h * 2 + 1]));
                                    }
                                }
                            }
                        }
                    }
                    if (!lastTile) __syncthreads();
                } else {
                    __syncthreads();
                }
            }
        }
    }
}

extern "C" void kernel_launch(void* const* d_in, const int* in_sizes, int n_in,
                              void* d_out, int out_size) {
    const float* x = nullptr;
    const void* batch = nullptr;
    const float* H = nullptr;
    for (int i = 0; i < n_in; i++) {
        int s = in_sizes[i];
        if (s == NODES * FDIM) x = (const float*)d_in[i];
        else if (s == NODES) batch = d_in[i];
        else if (s == NH * FDIM) H = (const float*)d_in[i];
    }
    unsigned* outu = (unsigned*)d_out;

    int nsm = 148;
    cudaDeviceGetAttribute(&nsm, cudaDevAttrMultiProcessorCount, 0);
    cudaFuncSetAttribute(mm_kernel, cudaFuncAttributeMaxDynamicSharedMemorySize, SMEM_BYTES);

    init_kernel<<<(NSEG * NH + 255) / 256, 256>>>(outu);
    mm_kernel<<<nsm, THREADS, SMEM_BYTES>>>(x, batch, H, outu);
    decode_kernel<<<(NSEG * NH + 255) / 256, 256>>>((float*)d_out);
}

// round 15
// speedup vs baseline: 1.3027x; 1.0363x over previous
#include <cuda_runtime.h>
#include <cuda_fp16.h>
#include <cstdint>

// MinHashSketch: sketch[s][h] = min over nodes m in segment s of dot(x[m], H[h]),
// empty segments -> 0.  x:[500000,256] f32, batch:[500000] i64/i32 (detected),
// H:[128,256] f32, out:[512,128] f32.
//
// Warp-specialized persistent fp16 m16n8k16 GEMM, 512 threads:
//   warps 8-15 (producers): LDG x -> cvt fp16 -> STS fragment-layout A chunks
//                           (BK=64) into a 2-deep ring, distance-1 prefetch.
//   warps 0-7  (consumers): LDS + mma only (mt2 x nt8 each; 2 mma warps per
//                           SMSP so LDS/barrier stalls are hidden), plus fused
//                           segment-min epilogue overlapped with the stream.
// B (=H) staged once per CTA. One barrier per chunk. Order-preserving uint
// encoding + atomicMin for the global segment-min.

#define NODES 500000
#define FDIM 256
#define NH   128
#define NSEG 512

#define BM   128
#define BK   64
#define CPT  (FDIM / BK)          // 4 chunks per tile
#define NKS  (FDIM / 16)          // 16 global k-steps
#define THREADS 512
#define NTILES ((NODES + BM - 1) / BM)   // 3907

// B fragment smem (b32 words, 2 fp16/word): 8 n-pairs * 16 ks * 132
#define B_KS_STRIDE   132
#define B_PAIR_STRIDE (NKS * B_KS_STRIDE)    // 2112
#define SM_B_WORDS    (8 * B_PAIR_STRIDE)    // 16896
// A fragment smem: per chunk 8 mt * 4 ksl * 132; 2 buffers
#define A_KS_STRIDE   132
#define A_MT_STRIDE   (4 * A_KS_STRIDE)      // 528
#define A_BUF_WORDS   (8 * A_MT_STRIDE)      // 4224
#define SM_A_OFF      SM_B_WORDS
#define SMEM_BYTES    ((SM_B_WORDS + 2 * A_BUF_WORDS) * 4)   // ~101 KB

__device__ __forceinline__ unsigned fenc(float f) {
    unsigned u = __float_as_uint(f);
    return (u & 0x80000000u) ? ~u : (u | 0x80000000u);
}

__device__ __forceinline__ unsigned packh2(float lo, float hi) {
    __half2 h = __floats2half2_rn(lo, hi);
    return *reinterpret_cast<unsigned*>(&h);
}

__device__ __forceinline__ void mma16(float* c, const unsigned* a, const unsigned* b) {
    asm volatile(
        "mma.sync.aligned.m16n8k16.row.col.f32.f16.f16.f32 "
        "{%0,%1,%2,%3}, {%4,%5,%6,%7}, {%8,%9}, {%0,%1,%2,%3};"
        : "+f"(c[0]), "+f"(c[1]), "+f"(c[2]), "+f"(c[3])
        : "r"(a[0]), "r"(a[1]), "r"(a[2]), "r"(a[3]), "r"(b[0]), "r"(b[1]));
}

__global__ void init_kernel(unsigned* outu) {
    int i = blockIdx.x * blockDim.x + threadIdx.x;
    if (i < NSEG * NH) outu[i] = 0xFFFFFFFFu;
}

__global__ void decode_kernel(float* out) {
    int i = blockIdx.x * blockDim.x + threadIdx.x;
    if (i < NSEG * NH) {
        unsigned u = __float_as_uint(out[i]);
        float f;
        if (u == 0xFFFFFFFFu) f = 0.0f;   // empty segment -> 0
        else f = (u & 0x80000000u) ? __uint_as_float(u ^ 0x80000000u) : __uint_as_float(~u);
        out[i] = f;
    }
}

// ---- producer helpers: chunk = [128 rows x 64 phys cols] of x, 256 threads ----
__device__ __forceinline__ void fetchA(float4* v, const float* __restrict__ x,
                                       int m0, int bk, int ptid) {
#pragma unroll
    for (int it = 0; it < 8; it++) {
        int idx = ptid + it * 256;
        int row = idx >> 4, col4 = idx & 15;
        int m = m0 + row;
        v[it] = (m < NODES)
            ? *(const float4*)(x + (size_t)m * FDIM + bk * BK + col4 * 4)
            : make_float4(0.f, 0.f, 0.f, 0.f);
    }
}

__device__ __forceinline__ void stsA(const float4* v, unsigned* Asm, int buf, int ptid) {
    unsigned* base = Asm + buf * A_BUF_WORDS;
#pragma unroll
    for (int it = 0; it < 8; it++) {
        int idx = ptid + it * 256;
        int row = idx >> 4, col4 = idx & 15;
        int mt = row >> 4, rr = row & 15;
        int g = rr & 7, hi = rr >> 3;
        int ksl = col4 >> 2, t4 = col4 & 3;
        int woff = mt * A_MT_STRIDE + ksl * A_KS_STRIDE + (g * 4 + t4) * 4 + hi * 2;
        uint2 w;
        w.x = packh2(v[it].x, v[it].y);   // klo pair
        w.y = packh2(v[it].z, v[it].w);   // khi pair
        *(uint2*)(base + woff) = w;       // per lane-uint4 word order: {a0,a2,a1,a3}
    }
}

__global__ void __launch_bounds__(THREADS, 1)
mm_kernel(const float* __restrict__ x, const void* __restrict__ batch_raw,
          const float* __restrict__ H, unsigned* __restrict__ outu) {
    extern __shared__ unsigned smw[];
    unsigned* Bfu = smw;
    unsigned* Asm = smw + SM_A_OFF;

    const int tid = threadIdx.x;
    const int wid = tid >> 5, lane = tid & 31;
    const int is64 = (((const int*)batch_raw)[NODES - 1] == 0);

    if (wid >= 8) {
        // ====================== PRODUCERS (warps 8-15) ======================
        const int ptid = tid - 256;
        int tp = blockIdx.x, bkp = 0;
        float4 v[8];
        fetchA(v, x, tp * BM, 0, ptid);
        stsA(v, Asm, 0, ptid);
        bkp = 1;
        fetchA(v, x, tp * BM, bkp, ptid);     // chunk 1 (CPT>=2 always)
        __syncthreads();                       // #0: buf0 full
        int buf = 1;
        for (;;) {
            stsA(v, Asm, buf, ptid);
            if (++bkp == CPT) { bkp = 0; tp += gridDim.x; }
            bool have = (tp < NTILES);
            if (have) fetchA(v, x, tp * BM, bkp, ptid);
            __syncthreads();
            buf ^= 1;
            if (!have) break;
        }
    } else {
        // ====================== CONSUMERS (warps 0-7) =======================
        const int wm = wid >> 1, wn = wid & 1;   // 4 (M) x 2 (N)
        const int tt = lane & 3;

        // Stage B = H once (k-permuted: logical {2t,2t+1,2t+8,2t+9} at phys 4t..4t+3)
        for (int i = tid; i < (NH * FDIM) / 4; i += 256) {
            int n = i >> 6;
            int col4 = i & 63;
            int ks = col4 >> 2, t4 = col4 & 3;
            float4 hv = ((const float4*)H)[i];
            int pp = n >> 4, half = (n >> 3) & 1;
            int lane0 = ((n & 7) << 2) | t4;
            unsigned* b = Bfu + pp * B_PAIR_STRIDE + ks * B_KS_STRIDE + lane0 * 4 + half * 2;
            b[0] = packh2(hv.x, hv.y);
            b[1] = packh2(hv.z, hv.w);
        }
        __syncthreads();                       // #0

        const unsigned* Bw = Bfu + wn * 4 * B_PAIR_STRIDE + lane * 4;
        int buf = 0;

        for (int t = blockIdx.x; t < NTILES; t += gridDim.x) {
            const int m0 = t * BM;
            const bool lastTile = (t + gridDim.x >= NTILES);

            float acc[2][8][4];
#pragma unroll
            for (int i = 0; i < 2; i++)
#pragma unroll
                for (int j = 0; j < 8; j++)
#pragma unroll
                    for (int c = 0; c < 4; c++) acc[i][j][c] = 0.f;

            for (int bk = 0; bk < CPT; bk++) {
                const unsigned* Ab = Asm + buf * A_BUF_WORDS + wm * 2 * A_MT_STRIDE + lane * 4;
#pragma unroll
                for (int ksl = 0; ksl < 4; ksl++) {
                    int ksg = bk * 4 + ksl;
                    uint4 av[2];
#pragma unroll
                    for (int i = 0; i < 2; i++)
                        av[i] = *(const uint4*)(Ab + i * A_MT_STRIDE + ksl * A_KS_STRIDE);
                    unsigned b[8][2];
#pragma unroll
                    for (int q = 0; q < 4; q++) {
                        uint4 bv = *(const uint4*)(Bw + q * B_PAIR_STRIDE + ksg * B_KS_STRIDE);
                        b[2 * q][0] = bv.x;     b[2 * q][1] = bv.y;
                        b[2 * q + 1][0] = bv.z; b[2 * q + 1][1] = bv.w;
                    }
#pragma unroll
                    for (int i = 0; i < 2; i++) {
                        unsigned a[4] = {av[i].x, av[i].z, av[i].y, av[i].w};
#pragma unroll
                        for (int j = 0; j < 8; j++)
                            mma16(acc[i][j], a, b[j]);
                    }
                }
                buf ^= 1;

                if (bk == CPT - 1) {
                    // ---- fused segment-min epilogue (inside last interval) ----
                    bool full = (m0 + BM) <= NODES;
                    int sF = is64 ? (int)((const long long*)batch_raw)[m0]
                                  : ((const int*)batch_raw)[m0];
                    int sL = -2;
                    if (full)
                        sL = is64 ? (int)((const long long*)batch_raw)[m0 + BM - 1]
                                  : ((const int*)batch_raw)[m0 + BM - 1];

                    if (full && sF == sL) {
#pragma unroll
                        for (int j = 0; j < 8; j++) {
                            float v0 = fminf(fminf(acc[0][j][0], acc[0][j][2]),
                                             fminf(acc[1][j][0], acc[1][j][2]));
                            float v1 = fminf(fminf(acc[0][j][1], acc[0][j][3]),
                                             fminf(acc[1][j][1], acc[1][j][3]));
#pragma unroll
                            for (int off = 4; off < 32; off <<= 1) {
                                v0 = fminf(v0, __shfl_xor_sync(0xffffffffu, v0, off));
                                v1 = fminf(v1, __shfl_xor_sync(0xffffffffu, v1, off));
                            }
                            if (lane < 4) {
                                int col = wn * 64 + j * 8 + lane * 2;
                                atomicMin(&outu[sF * NH + col],     fenc(v0));
                                atomicMin(&outu[sF * NH + col + 1], fenc(v1));
                            }
                        }
                    } else {
                        const int g = lane >> 2;
#pragma unroll
                        for (int i = 0; i < 2; i++) {
#pragma unroll
                            for (int h = 0; h < 2; h++) {
                                int m = m0 + wm * 32 + i * 16 + g + h * 8;
                                if (m < NODES) {
                                    int s = is64 ? (int)((const long long*)batch_raw)[m]
                                                 : ((const int*)batch_raw)[m];
                                    unsigned* dst = outu + s * NH + wn * 64 + tt * 2;
#pragma unroll
                                    for (int j = 0; j < 8; j++) {
                                        atomicMin(dst + j * 8,     fenc(acc[i][j][h * 2 + 0]));
                                        atomicMin(dst + j * 8 + 1, fenc(acc[i][j][h * 2 + 1]));
                                    }
                                }
                            }
                        }
                    }
                    if (!lastTile) __syncthreads();
                } else {
                    __syncthreads();
                }
            }
        }
    }
}

extern "C" void kernel_launch(void* const* d_in, const int* in_sizes, int n_in,
                              void* d_out, int out_size) {
    const float* x = nullptr;
    const void* batch = nullptr;
    const float* H = nullptr;
    for (int i = 0; i < n_in; i++) {
        int s = in_sizes[i];
        if (s == NODES * FDIM) x = (const float*)d_in[i];
        else if (s == NODES) batch = d_in[i];
        else if (s == NH * FDIM) H = (const float*)d_in[i];
    }
    unsigned* outu = (unsigned*)d_out;

    int nsm = 148;
    cudaDeviceGetAttribute(&nsm, cudaDevAttrMultiProcessorCount, 0);
    cudaFuncSetAttribute(mm_kernel, cudaFuncAttributeMaxDynamicSharedMemorySize, SMEM_BYTES);

    init_kernel<<<(NSEG * NH + 255) / 256, 256>>>(outu);
    mm_kernel<<<nsm, THREADS, SMEM_BYTES>>>(x, batch, H, outu);
    decode_kernel<<<(NSEG * NH + 255) / 256, 256>>>((float*)d_out);
}